// round 8
// baseline (speedup 1.0000x reference)
#include <cuda_runtime.h>
#include <math.h>

#define N_ROWS 131072   // 32*64*64
#define DIM    64
#define KCB    512

// Output layout (concatenated, float32). Scalar perplexity misaligns
// everything after it to 4B -> scalar stores only into outE/outD.
#define OFF_Q 0
#define OFF_P (N_ROWS * DIM)
#define OFF_E (OFF_P + 1)
#define OFF_I (OFF_E + (size_t)N_ROWS * KCB)
#define OFF_D (OFF_I + N_ROWS)

#define CAND_CAP 16
#define CAND_MARGIN 1e-3f

// Scratch
__device__ float g_rownorm[N_ROWS];
__device__ float g_colnorm[KCB];
__device__ unsigned int g_count[KCB];
__device__ int g_candn[N_ROWS];
__device__ unsigned short g_cand[N_ROWS][CAND_CAP];

// ---------------------------------------------------------------------------
__device__ __forceinline__ unsigned int forder(float f) {
    unsigned int u = __float_as_uint(f);
    unsigned int mask = ((int)u >> 31) | 0x80000000u;
    return u ^ mask;  // monotonic float -> uint
}

__device__ __forceinline__ float cvt_tf32(float v) {
    unsigned r;
    asm("cvt.rna.tf32.f32 %0, %1;" : "=r"(r) : "f"(v));
    return __uint_as_float(r);
}

__device__ __forceinline__ void mma8(float* c, const float* a, const float* b) {
    asm volatile(
        "mma.sync.aligned.m16n8k8.row.col.f32.tf32.tf32.f32 "
        "{%0,%1,%2,%3}, {%4,%5,%6,%7}, {%8,%9}, {%0,%1,%2,%3};"
        : "+f"(c[0]), "+f"(c[1]), "+f"(c[2]), "+f"(c[3])
        : "r"(__float_as_uint(a[0])), "r"(__float_as_uint(a[1])),
          "r"(__float_as_uint(a[2])), "r"(__float_as_uint(a[3])),
          "r"(__float_as_uint(b[0])), "r"(__float_as_uint(b[1])));
}

// ---------------------------------------------------------------------------
__global__ void rownorm_k(const float* __restrict__ X) {
    int r = blockIdx.x * blockDim.x + threadIdx.x;
    if (r >= N_ROWS) return;
    g_candn[r] = 0;
    const float4* p = (const float4*)(X + (size_t)r * DIM);
    float s = 0.f;
#pragma unroll
    for (int i = 0; i < DIM / 4; i++) {
        float4 v = p[i];
        s += v.x * v.x + v.y * v.y + v.z * v.z + v.w * v.w;
    }
    g_rownorm[r] = s;
}

__global__ void colnorm_k(const float* __restrict__ CB) {
    int r = blockIdx.x * blockDim.x + threadIdx.x;
    if (r >= KCB) return;
    g_count[r] = 0u;
    const float4* p = (const float4*)(CB + (size_t)r * DIM);
    float s = 0.f;
#pragma unroll
    for (int i = 0; i < DIM / 4; i++) {
        float4 v = p[i];
        s += v.x * v.x + v.y * v.y + v.z * v.z + v.w * v.w;
    }
    g_colnorm[r] = s;
}

// ---------------------------------------------------------------------------
// tensor-core distance GEMM (single tf32 MMA) + candidate collection
// + encodings zero-fill (each CTA zeroes its 128x128 encodings patch;
// rescue_k overwrites the single 1.0 afterwards in stream order).
// CTA 128x128, K=64 resident, 8 warps, warp tile 32x64. 3 CTAs/SM target.
// ---------------------------------------------------------------------------
#define AS_STRIDE 68
#define CS_STRIDE 132
#define GEMM_SMEM_BYTES (2 * 128 * AS_STRIDE * 4)

__global__ __launch_bounds__(256, 3) void gemm_k(const float* __restrict__ A,
                                                 const float* __restrict__ B,
                                                 float* __restrict__ outD,
                                                 float* __restrict__ outE) {
    extern __shared__ float sm[];
    float* As = sm;                      // [128][68] tf32(A)
    float* Bs = sm + 128 * AS_STRIDE;    // [128][68] tf32(2*codebook)
    float* Cs = sm;                      // [128][132] aliases post-MMA

    const int tid = threadIdx.x;
    const int lane = tid & 31;
    const int wid = tid >> 5;
    const int g = lane >> 2;
    const int t = lane & 3;
    const int wm0 = (wid & 3) * 32;
    const int wn0 = (wid >> 2) * 64;
    const int bm0 = blockIdx.y * 128;
    const int bk0 = blockIdx.x * 128;

    {
        const float4* Ag = (const float4*)(A + (size_t)bm0 * DIM);
        const float4* Bg = (const float4*)(B + (size_t)bk0 * DIM);
#pragma unroll
        for (int i = 0; i < 8; i++) {
            int t4 = tid + i * 256;        // 0..2047
            int row = t4 >> 4;
            int c4 = (t4 & 15) * 4;
            float4 va = Ag[t4];
            float4 vh;
            vh.x = cvt_tf32(va.x);
            vh.y = cvt_tf32(va.y);
            vh.z = cvt_tf32(va.z);
            vh.w = cvt_tf32(va.w);
            *(float4*)&As[row * AS_STRIDE + c4] = vh;
            float4 vb = Bg[t4];
            float4 bh;
            bh.x = cvt_tf32(2.f * vb.x);
            bh.y = cvt_tf32(2.f * vb.y);
            bh.z = cvt_tf32(2.f * vb.z);
            bh.w = cvt_tf32(2.f * vb.w);
            *(float4*)&Bs[row * AS_STRIDE + c4] = bh;
        }
    }
    __syncthreads();

    float acc[2][8][4];
#pragma unroll
    for (int mi = 0; mi < 2; mi++)
#pragma unroll
        for (int ni = 0; ni < 8; ni++)
#pragma unroll
            for (int j = 0; j < 4; j++) acc[mi][ni][j] = 0.f;

#pragma unroll
    for (int k0 = 0; k0 < 64; k0 += 8) {
        float ah[2][4];
#pragma unroll
        for (int mi = 0; mi < 2; mi++) {
            int r0 = wm0 + mi * 16 + g;
            ah[mi][0] = As[r0 * AS_STRIDE + k0 + t];
            ah[mi][1] = As[(r0 + 8) * AS_STRIDE + k0 + t];
            ah[mi][2] = As[r0 * AS_STRIDE + k0 + t + 4];
            ah[mi][3] = As[(r0 + 8) * AS_STRIDE + k0 + t + 4];
        }
#pragma unroll
        for (int nh = 0; nh < 2; nh++) {
            float bh[4][2];
#pragma unroll
            for (int ni = 0; ni < 4; ni++) {
                int n = wn0 + (nh * 4 + ni) * 8 + g;
                bh[ni][0] = Bs[n * AS_STRIDE + k0 + t];
                bh[ni][1] = Bs[n * AS_STRIDE + k0 + t + 4];
            }
#pragma unroll
            for (int mi = 0; mi < 2; mi++)
#pragma unroll
                for (int ni = 0; ni < 4; ni++)
                    mma8(acc[mi][nh * 4 + ni], ah[mi], bh[ni]);
        }
    }

    __syncthreads();
#pragma unroll
    for (int mi = 0; mi < 2; mi++)
#pragma unroll
        for (int ni = 0; ni < 8; ni++) {
            int r0 = wm0 + mi * 16 + g;
            int c0 = wn0 + ni * 8 + 2 * t;
            Cs[r0 * CS_STRIDE + c0]           = acc[mi][ni][0];
            Cs[r0 * CS_STRIDE + c0 + 1]       = acc[mi][ni][1];
            Cs[(r0 + 8) * CS_STRIDE + c0]     = acc[mi][ni][2];
            Cs[(r0 + 8) * CS_STRIDE + c0 + 1] = acc[mi][ni][3];
        }
    __syncthreads();

    // Distance stores + candidate collection + encodings zero-fill.
    float cn4[4];
#pragma unroll
    for (int j = 0; j < 4; j++) cn4[j] = g_colnorm[bk0 + lane + 32 * j];

#pragma unroll 2
    for (int r = 0; r < 16; r++) {
        int lr = wid * 16 + r;
        int gr = bm0 + lr;
        float rn = g_rownorm[gr];
        const float* crow = &Cs[lr * CS_STRIDE];
        float* drow = outD + (size_t)gr * KCB + bk0;
        float* erow = outE + (size_t)gr * KCB + bk0;
        float v[4];
        float mn = 3.4e38f;
#pragma unroll
        for (int j = 0; j < 4; j++) {
            int c = lane + 32 * j;
            float d = (rn - crow[c]) + cn4[j];
            v[j] = d;
            drow[c] = d;
            erow[c] = 0.f;
            if (d < mn) mn = d;
        }
#pragma unroll
        for (int off = 16; off > 0; off >>= 1) {
            float o = __shfl_xor_sync(0xFFFFFFFFu, mn, off);
            if (o < mn) mn = o;
        }
        float thr = mn + CAND_MARGIN;
#pragma unroll
        for (int j = 0; j < 4; j++) {
            if (v[j] <= thr) {
                int slot = atomicAdd(&g_candn[gr], 1);
                if (slot < CAND_CAP)
                    g_cand[gr][slot] = (unsigned short)(bk0 + lane + 32 * j);
            }
        }
    }
}

// ---------------------------------------------------------------------------
// rescue + outputs: block = 32 rows, 8 threads/row. Candidates processed
// SERIALLY by the 8-lane group: each lane loads 2 contiguous float4 of the
// candidate's codebook row (full 256B row per group -> coalesced), partial
// 8-elem dot, 3 xor-shfl reduce (broadcasts the sum to all 8 lanes).
// Exact fp32 numerics. Writes indices, histogram, one-hot 1.0, quantized.
// ---------------------------------------------------------------------------
#define RROWS 32   // rows per block
__global__ __launch_bounds__(256, 4) void rescue_k(const float* __restrict__ X,
                                                   const float* __restrict__ CB,
                                                   float* __restrict__ outI,
                                                   float* __restrict__ outE,
                                                   float* __restrict__ outQ) {
    __shared__ float Xs[RROWS * DIM];           // 8 KB
    const int tid = threadIdx.x;
    const int r = tid >> 3;        // 0..31 row within block
    const int s = tid & 7;         // lane within row group
    const int row0 = blockIdx.x * RROWS;
    const int gr = row0 + r;

    // cooperative X stage: 32 rows x 64 floats = 512 float4
    {
        const float4* Xg = (const float4*)(X + (size_t)row0 * DIM);
        float4* Xs4 = (float4*)Xs;
#pragma unroll
        for (int i = 0; i < 2; i++) Xs4[tid + i * 256] = Xg[tid + i * 256];
    }
    __syncthreads();

    const float rn = g_rownorm[gr];
    const float4* xp4 = (const float4*)(Xs + r * DIM);
    const int n = g_candn[gr];

    unsigned long long best = 0xFFFFFFFFFFFFFFFFULL;
    if (n <= CAND_CAP) {
        // this thread's 8-element slice of x (held in registers)
        float4 x0 = xp4[s * 2];
        float4 x1 = xp4[s * 2 + 1];
        for (int j = 0; j < n; j++) {
            int c = g_cand[gr][j];
            const float4* cp4 = (const float4*)(CB + (size_t)c * DIM);
            float4 e0 = cp4[s * 2];
            float4 e1 = cp4[s * 2 + 1];
            float p = x0.x * e0.x;
            p = fmaf(x0.y, e0.y, p);
            p = fmaf(x0.z, e0.z, p);
            p = fmaf(x0.w, e0.w, p);
            p = fmaf(x1.x, e1.x, p);
            p = fmaf(x1.y, e1.y, p);
            p = fmaf(x1.z, e1.z, p);
            p = fmaf(x1.w, e1.w, p);
            // reduce within 8-lane group (xor 4/2/1 stays in group); all lanes
            // end with the same sum -> identical best across the group
            p += __shfl_xor_sync(0xFFFFFFFFu, p, 4);
            p += __shfl_xor_sync(0xFFFFFFFFu, p, 2);
            p += __shfl_xor_sync(0xFFFFFFFFu, p, 1);
            float d = (rn - 2.f * p) + g_colnorm[c];
            unsigned long long key =
                ((unsigned long long)forder(d) << 32) | (unsigned)c;
            if (key < best) best = key;
        }
    } else {
        // overflow fallback (rare): per-lane scan of all 512 codes
        for (int c = s; c < KCB; c += 8) {
            const float4* cp4 = (const float4*)(CB + (size_t)c * DIM);
            float d0 = 0.f, d1 = 0.f, d2 = 0.f, d3 = 0.f;
#pragma unroll
            for (int i = 0; i < DIM / 4; i++) {
                float4 x = xp4[i];
                float4 e = cp4[i];
                d0 = fmaf(x.x, e.x, d0);
                d1 = fmaf(x.y, e.y, d1);
                d2 = fmaf(x.z, e.z, d2);
                d3 = fmaf(x.w, e.w, d3);
            }
            float dot = (d0 + d1) + (d2 + d3);
            float d = (rn - 2.f * dot) + g_colnorm[c];
            unsigned long long key =
                ((unsigned long long)forder(d) << 32) | (unsigned)c;
            if (key < best) best = key;
        }
#pragma unroll
        for (int off = 4; off > 0; off >>= 1) {
            unsigned long long o = __shfl_xor_sync(0xFFFFFFFFu, best, off);
            if (o < best) best = o;
        }
    }
    int idx = (int)(best & 0xFFFFFFFFu);

    if (s == 0) {
        outI[gr] = (float)idx;
        atomicAdd(&g_count[idx], 1u);
        outE[(size_t)gr * KCB + idx] = 1.f;  // zeros pre-filled by gemm_k
    }

    // quantized: 8 threads x 8 floats (2 float4 each); outQ 16B-aligned
    {
        const float4* cp4 = (const float4*)(CB + (size_t)idx * DIM);
        float4* qp4 = (float4*)(outQ + (size_t)gr * DIM);
#pragma unroll
        for (int i = 0; i < 2; i++) {
            int j = s * 2 + i;
            float4 x = xp4[j];
            float4 e = cp4[j];
            float4 q;
            q.x = x.x + (e.x - x.x);
            q.y = x.y + (e.y - x.y);
            q.z = x.z + (e.z - x.z);
            q.w = x.w + (e.w - x.w);
            qp4[j] = q;
        }
    }
}

// ---------------------------------------------------------------------------
__global__ void perp_k(float* __restrict__ outP) {
    __shared__ float s[KCB];
    int t = threadIdx.x;
    float p = (float)g_count[t] / (float)N_ROWS;
    s[t] = p * logf(p + 1e-10f);
    __syncthreads();
    for (int o = KCB / 2; o > 0; o >>= 1) {
        if (t < o) s[t] += s[t + o];
        __syncthreads();
    }
    if (t == 0) outP[0] = expf(-s[0]);
}

// ---------------------------------------------------------------------------
extern "C" void kernel_launch(void* const* d_in, const int* in_sizes, int n_in,
                              void* d_out, int out_size) {
    const float* X = (const float*)d_in[0];
    const float* CB = (const float*)d_in[1];
    if (n_in >= 2 && in_sizes[0] == KCB * DIM) {
        X = (const float*)d_in[1];
        CB = (const float*)d_in[0];
    }
    float* out = (float*)d_out;
    float* outQ = out + OFF_Q;
    float* outP = out + OFF_P;
    float* outE = out + OFF_E;
    float* outI = out + OFF_I;
    float* outD = out + OFF_D;

    cudaFuncSetAttribute(gemm_k, cudaFuncAttributeMaxDynamicSharedMemorySize,
                         GEMM_SMEM_BYTES);

    rownorm_k<<<N_ROWS / 256, 256>>>(X);
    colnorm_k<<<2, 256>>>(CB);
    gemm_k<<<dim3(KCB / 128, N_ROWS / 128), 256, GEMM_SMEM_BYTES>>>(X, CB, outD, outE);
    rescue_k<<<N_ROWS / RROWS, 256>>>(X, CB, outI, outE, outQ);
    perp_k<<<1, KCB>>>(outP);
}

// round 9
// speedup vs baseline: 1.1635x; 1.1635x over previous
#include <cuda_runtime.h>
#include <math.h>

#define N_ROWS 131072   // 32*64*64
#define DIM    64
#define KCB    512

// Output layout (concatenated, float32). Scalar perplexity misaligns
// everything after it to 4B -> scalar stores only into outE/outD.
#define OFF_Q 0
#define OFF_P (N_ROWS * DIM)
#define OFF_E (OFF_P + 1)
#define OFF_I (OFF_E + (size_t)N_ROWS * KCB)
#define OFF_D (OFF_I + N_ROWS)

#define CAND_CAP 16
#define CAND_MARGIN 1e-3f

// Scratch
__device__ float g_rownorm[N_ROWS];
__device__ float g_colnorm[KCB];
__device__ unsigned int g_count[KCB];
__device__ int g_candn[N_ROWS];
__device__ unsigned short g_cand[N_ROWS][CAND_CAP];

// ---------------------------------------------------------------------------
__device__ __forceinline__ unsigned int forder(float f) {
    unsigned int u = __float_as_uint(f);
    unsigned int mask = ((int)u >> 31) | 0x80000000u;
    return u ^ mask;  // monotonic float -> uint
}

__device__ __forceinline__ float cvt_tf32(float v) {
    unsigned r;
    asm("cvt.rna.tf32.f32 %0, %1;" : "=r"(r) : "f"(v));
    return __uint_as_float(r);
}

__device__ __forceinline__ void mma8(float* c, const float* a, const float* b) {
    asm volatile(
        "mma.sync.aligned.m16n8k8.row.col.f32.tf32.tf32.f32 "
        "{%0,%1,%2,%3}, {%4,%5,%6,%7}, {%8,%9}, {%0,%1,%2,%3};"
        : "+f"(c[0]), "+f"(c[1]), "+f"(c[2]), "+f"(c[3])
        : "r"(__float_as_uint(a[0])), "r"(__float_as_uint(a[1])),
          "r"(__float_as_uint(a[2])), "r"(__float_as_uint(a[3])),
          "r"(__float_as_uint(b[0])), "r"(__float_as_uint(b[1])));
}

// ---------------------------------------------------------------------------
__global__ void rownorm_k(const float* __restrict__ X) {
    int r = blockIdx.x * blockDim.x + threadIdx.x;
    if (r >= N_ROWS) return;
    g_candn[r] = 0;
    const float4* p = (const float4*)(X + (size_t)r * DIM);
    float s = 0.f;
#pragma unroll
    for (int i = 0; i < DIM / 4; i++) {
        float4 v = p[i];
        s += v.x * v.x + v.y * v.y + v.z * v.z + v.w * v.w;
    }
    g_rownorm[r] = s;
}

__global__ void colnorm_k(const float* __restrict__ CB) {
    int r = blockIdx.x * blockDim.x + threadIdx.x;
    if (r >= KCB) return;
    g_count[r] = 0u;
    const float4* p = (const float4*)(CB + (size_t)r * DIM);
    float s = 0.f;
#pragma unroll
    for (int i = 0; i < DIM / 4; i++) {
        float4 v = p[i];
        s += v.x * v.x + v.y * v.y + v.z * v.z + v.w * v.w;
    }
    g_colnorm[r] = s;
}

// ---------------------------------------------------------------------------
// tensor-core distance GEMM (single tf32 MMA) + candidate collection
// + encodings zero-fill. CTA 128x128, K=64 resident, 8 warps, 32x64/warp.
// smem k-layout permuted within each 8-block: pos(k) = (k&3)*2 + (k>>2),
// so fragment pairs (k=t, k=t+4) are one contiguous float2 -> LDS.64.
// ---------------------------------------------------------------------------
#define AS_STRIDE 68
#define CS_STRIDE 132
#define GEMM_SMEM_BYTES (2 * 128 * AS_STRIDE * 4)

__global__ __launch_bounds__(256) void gemm_k(const float* __restrict__ A,
                                              const float* __restrict__ B,
                                              float* __restrict__ outD,
                                              float* __restrict__ outE) {
    extern __shared__ float sm[];
    float* As = sm;                      // [128][68] tf32(A), k-permuted
    float* Bs = sm + 128 * AS_STRIDE;    // [128][68] tf32(2*codebook), k-perm
    float* Cs = sm;                      // [128][132] aliases post-MMA

    const int tid = threadIdx.x;
    const int lane = tid & 31;
    const int wid = tid >> 5;
    const int g = lane >> 2;
    const int t = lane & 3;
    const int wm0 = (wid & 3) * 32;
    const int wn0 = (wid >> 2) * 64;
    const int bm0 = blockIdx.y * 128;
    const int bk0 = blockIdx.x * 128;

    // Tile load with one-time tf32 cvt + k-permuted scatter.
    // float4 covers k = c4..c4+3; perm positions: base + off + {0,2,4,6}
    // where base = c4 & ~7, off = (c4 & 4) >> 2.
    {
        const float4* Ag = (const float4*)(A + (size_t)bm0 * DIM);
        const float4* Bg = (const float4*)(B + (size_t)bk0 * DIM);
#pragma unroll
        for (int i = 0; i < 8; i++) {
            int t4 = tid + i * 256;        // 0..2047
            int row = t4 >> 4;
            int c4 = (t4 & 15) * 4;
            int base = (c4 & ~7) + ((c4 & 4) >> 2);
            float* ap = &As[row * AS_STRIDE + base];
            float* bp = &Bs[row * AS_STRIDE + base];
            float4 va = Ag[t4];
            ap[0] = cvt_tf32(va.x);
            ap[2] = cvt_tf32(va.y);
            ap[4] = cvt_tf32(va.z);
            ap[6] = cvt_tf32(va.w);
            float4 vb = Bg[t4];
            bp[0] = cvt_tf32(2.f * vb.x);
            bp[2] = cvt_tf32(2.f * vb.y);
            bp[4] = cvt_tf32(2.f * vb.z);
            bp[6] = cvt_tf32(2.f * vb.w);
        }
    }
    __syncthreads();

    float acc[2][8][4];
#pragma unroll
    for (int mi = 0; mi < 2; mi++)
#pragma unroll
        for (int ni = 0; ni < 8; ni++)
#pragma unroll
            for (int j = 0; j < 4; j++) acc[mi][ni][j] = 0.f;

#pragma unroll
    for (int k0 = 0; k0 < 64; k0 += 8) {
        // A fragments: LDS.64 pairs (a0,a2) row r0, (a1,a3) row r0+8
        float ah[2][4];
#pragma unroll
        for (int mi = 0; mi < 2; mi++) {
            int r0 = wm0 + mi * 16 + g;
            float2 fa0 = *(const float2*)&As[r0 * AS_STRIDE + k0 + 2 * t];
            float2 fa1 = *(const float2*)&As[(r0 + 8) * AS_STRIDE + k0 + 2 * t];
            ah[mi][0] = fa0.x;
            ah[mi][1] = fa1.x;
            ah[mi][2] = fa0.y;
            ah[mi][3] = fa1.y;
        }
#pragma unroll
        for (int nh = 0; nh < 2; nh++) {
            float bh[4][2];
#pragma unroll
            for (int ni = 0; ni < 4; ni++) {
                int n = wn0 + (nh * 4 + ni) * 8 + g;
                float2 fb = *(const float2*)&Bs[n * AS_STRIDE + k0 + 2 * t];
                bh[ni][0] = fb.x;
                bh[ni][1] = fb.y;
            }
#pragma unroll
            for (int mi = 0; mi < 2; mi++)
#pragma unroll
                for (int ni = 0; ni < 4; ni++)
                    mma8(acc[mi][nh * 4 + ni], ah[mi], bh[ni]);
        }
    }

    __syncthreads();
    // Stage accumulators via STS.64 (c0 even -> 8B aligned)
#pragma unroll
    for (int mi = 0; mi < 2; mi++)
#pragma unroll
        for (int ni = 0; ni < 8; ni++) {
            int r0 = wm0 + mi * 16 + g;
            int c0 = wn0 + ni * 8 + 2 * t;
            *(float2*)&Cs[r0 * CS_STRIDE + c0] =
                make_float2(acc[mi][ni][0], acc[mi][ni][1]);
            *(float2*)&Cs[(r0 + 8) * CS_STRIDE + c0] =
                make_float2(acc[mi][ni][2], acc[mi][ni][3]);
        }
    __syncthreads();

    // Distance stores + candidate collection + encodings zero-fill.
    float cn4[4];
#pragma unroll
    for (int j = 0; j < 4; j++) cn4[j] = g_colnorm[bk0 + lane + 32 * j];

#pragma unroll 2
    for (int r = 0; r < 16; r++) {
        int lr = wid * 16 + r;
        int gr = bm0 + lr;
        float rn = g_rownorm[gr];
        const float* crow = &Cs[lr * CS_STRIDE];
        float* drow = outD + (size_t)gr * KCB + bk0;
        float* erow = outE + (size_t)gr * KCB + bk0;
        float v[4];
        float mn = 3.4e38f;
#pragma unroll
        for (int j = 0; j < 4; j++) {
            int c = lane + 32 * j;
            float d = (rn - crow[c]) + cn4[j];
            v[j] = d;
            drow[c] = d;
            erow[c] = 0.f;
            if (d < mn) mn = d;
        }
#pragma unroll
        for (int off = 16; off > 0; off >>= 1) {
            float o = __shfl_xor_sync(0xFFFFFFFFu, mn, off);
            if (o < mn) mn = o;
        }
        float thr = mn + CAND_MARGIN;
#pragma unroll
        for (int j = 0; j < 4; j++) {
            if (v[j] <= thr) {
                int slot = atomicAdd(&g_candn[gr], 1);
                if (slot < CAND_CAP)
                    g_cand[gr][slot] = (unsigned short)(bk0 + lane + 32 * j);
            }
        }
    }
}

// ---------------------------------------------------------------------------
// rescue + outputs: block = 32 rows, 8 threads/row. Candidates processed
// serially by the 8-lane group (coalesced codebook reads), two at a time so
// the shfl-reduce chains pipeline. Per-8-group shfl masks (groups within a
// warp have different trip counts -> full-warp masks would be UB).
// Exact fp32 numerics. Writes indices, histogram, one-hot 1.0, quantized.
// ---------------------------------------------------------------------------
#define RROWS 32   // rows per block
__global__ __launch_bounds__(256, 4) void rescue_k(const float* __restrict__ X,
                                                   const float* __restrict__ CB,
                                                   float* __restrict__ outI,
                                                   float* __restrict__ outE,
                                                   float* __restrict__ outQ) {
    __shared__ float Xs[RROWS * DIM];           // 8 KB
    const int tid = threadIdx.x;
    const int r = tid >> 3;        // 0..31 row within block
    const int s = tid & 7;         // lane within row group
    const int lane = tid & 31;
    const unsigned gmask = 0xFFu << (lane & 24);   // this 8-group's lanes
    const int row0 = blockIdx.x * RROWS;
    const int gr = row0 + r;

    // cooperative X stage: 32 rows x 64 floats = 512 float4
    {
        const float4* Xg = (const float4*)(X + (size_t)row0 * DIM);
        float4* Xs4 = (float4*)Xs;
#pragma unroll
        for (int i = 0; i < 2; i++) Xs4[tid + i * 256] = Xg[tid + i * 256];
    }
    __syncthreads();

    const float rn = g_rownorm[gr];
    const float4* xp4 = (const float4*)(Xs + r * DIM);
    const int n = g_candn[gr];

    unsigned long long best = 0xFFFFFFFFFFFFFFFFULL;
    if (n <= CAND_CAP) {
        float4 x0 = xp4[s * 2];
        float4 x1 = xp4[s * 2 + 1];
        int j = 0;
        for (; j + 1 < n; j += 2) {
            int c0 = g_cand[gr][j];
            int c1 = g_cand[gr][j + 1];
            const float4* e0p = (const float4*)(CB + (size_t)c0 * DIM);
            const float4* e1p = (const float4*)(CB + (size_t)c1 * DIM);
            float4 a0 = e0p[s * 2], a1 = e0p[s * 2 + 1];
            float4 b0 = e1p[s * 2], b1 = e1p[s * 2 + 1];
            float p = x0.x * a0.x;
            p = fmaf(x0.y, a0.y, p); p = fmaf(x0.z, a0.z, p);
            p = fmaf(x0.w, a0.w, p); p = fmaf(x1.x, a1.x, p);
            p = fmaf(x1.y, a1.y, p); p = fmaf(x1.z, a1.z, p);
            p = fmaf(x1.w, a1.w, p);
            float q = x0.x * b0.x;
            q = fmaf(x0.y, b0.y, q); q = fmaf(x0.z, b0.z, q);
            q = fmaf(x0.w, b0.w, q); q = fmaf(x1.x, b1.x, q);
            q = fmaf(x1.y, b1.y, q); q = fmaf(x1.z, b1.z, q);
            q = fmaf(x1.w, b1.w, q);
            p += __shfl_xor_sync(gmask, p, 4);
            q += __shfl_xor_sync(gmask, q, 4);
            p += __shfl_xor_sync(gmask, p, 2);
            q += __shfl_xor_sync(gmask, q, 2);
            p += __shfl_xor_sync(gmask, p, 1);
            q += __shfl_xor_sync(gmask, q, 1);
            float d0 = (rn - 2.f * p) + g_colnorm[c0];
            float d1 = (rn - 2.f * q) + g_colnorm[c1];
            unsigned long long k0 =
                ((unsigned long long)forder(d0) << 32) | (unsigned)c0;
            unsigned long long k1 =
                ((unsigned long long)forder(d1) << 32) | (unsigned)c1;
            if (k0 < best) best = k0;
            if (k1 < best) best = k1;
        }
        if (j < n) {
            int c0 = g_cand[gr][j];
            const float4* e0p = (const float4*)(CB + (size_t)c0 * DIM);
            float4 a0 = e0p[s * 2], a1 = e0p[s * 2 + 1];
            float p = x0.x * a0.x;
            p = fmaf(x0.y, a0.y, p); p = fmaf(x0.z, a0.z, p);
            p = fmaf(x0.w, a0.w, p); p = fmaf(x1.x, a1.x, p);
            p = fmaf(x1.y, a1.y, p); p = fmaf(x1.z, a1.z, p);
            p = fmaf(x1.w, a1.w, p);
            p += __shfl_xor_sync(gmask, p, 4);
            p += __shfl_xor_sync(gmask, p, 2);
            p += __shfl_xor_sync(gmask, p, 1);
            float d0 = (rn - 2.f * p) + g_colnorm[c0];
            unsigned long long k0 =
                ((unsigned long long)forder(d0) << 32) | (unsigned)c0;
            if (k0 < best) best = k0;
        }
    } else {
        // overflow fallback (rare): per-lane scan of all 512 codes
        for (int c = s; c < KCB; c += 8) {
            const float4* cp4 = (const float4*)(CB + (size_t)c * DIM);
            float d0 = 0.f, d1 = 0.f, d2 = 0.f, d3 = 0.f;
#pragma unroll
            for (int i = 0; i < DIM / 4; i++) {
                float4 x = xp4[i];
                float4 e = cp4[i];
                d0 = fmaf(x.x, e.x, d0);
                d1 = fmaf(x.y, e.y, d1);
                d2 = fmaf(x.z, e.z, d2);
                d3 = fmaf(x.w, e.w, d3);
            }
            float dot = (d0 + d1) + (d2 + d3);
            float d = (rn - 2.f * dot) + g_colnorm[c];
            unsigned long long key =
                ((unsigned long long)forder(d) << 32) | (unsigned)c;
            if (key < best) best = key;
        }
#pragma unroll
        for (int off = 4; off > 0; off >>= 1) {
            unsigned long long o = __shfl_xor_sync(gmask, best, off);
            if (o < best) best = o;
        }
    }
    int idx = (int)(best & 0xFFFFFFFFu);

    if (s == 0) {
        outI[gr] = (float)idx;
        atomicAdd(&g_count[idx], 1u);
        outE[(size_t)gr * KCB + idx] = 1.f;  // zeros pre-filled by gemm_k
    }

    // quantized: 8 threads x 8 floats (2 float4 each); outQ 16B-aligned
    {
        const float4* cp4 = (const float4*)(CB + (size_t)idx * DIM);
        float4* qp4 = (float4*)(outQ + (size_t)gr * DIM);
#pragma unroll
        for (int i = 0; i < 2; i++) {
            int j = s * 2 + i;
            float4 x = xp4[j];
            float4 e = cp4[j];
            float4 q;
            q.x = x.x + (e.x - x.x);
            q.y = x.y + (e.y - x.y);
            q.z = x.z + (e.z - x.z);
            q.w = x.w + (e.w - x.w);
            qp4[j] = q;
        }
    }
}

// ---------------------------------------------------------------------------
__global__ void perp_k(float* __restrict__ outP) {
    __shared__ float s[KCB];
    int t = threadIdx.x;
    float p = (float)g_count[t] / (float)N_ROWS;
    s[t] = p * logf(p + 1e-10f);
    __syncthreads();
    for (int o = KCB / 2; o > 0; o >>= 1) {
        if (t < o) s[t] += s[t + o];
        __syncthreads();
    }
    if (t == 0) outP[0] = expf(-s[0]);
}

// ---------------------------------------------------------------------------
extern "C" void kernel_launch(void* const* d_in, const int* in_sizes, int n_in,
                              void* d_out, int out_size) {
    const float* X = (const float*)d_in[0];
    const float* CB = (const float*)d_in[1];
    if (n_in >= 2 && in_sizes[0] == KCB * DIM) {
        X = (const float*)d_in[1];
        CB = (const float*)d_in[0];
    }
    float* out = (float*)d_out;
    float* outQ = out + OFF_Q;
    float* outP = out + OFF_P;
    float* outE = out + OFF_E;
    float* outI = out + OFF_I;
    float* outD = out + OFF_D;

    cudaFuncSetAttribute(gemm_k, cudaFuncAttributeMaxDynamicSharedMemorySize,
                         GEMM_SMEM_BYTES);

    rownorm_k<<<N_ROWS / 256, 256>>>(X);
    colnorm_k<<<2, 256>>>(CB);
    gemm_k<<<dim3(KCB / 128, N_ROWS / 128), 256, GEMM_SMEM_BYTES>>>(X, CB, outD, outE);
    rescue_k<<<N_ROWS / RROWS, 256>>>(X, CB, outI, outE, outQ);
    perp_k<<<1, KCB>>>(outP);
}

// round 10
// speedup vs baseline: 1.2199x; 1.0485x over previous
#include <cuda_runtime.h>
#include <math.h>

#define N_ROWS 131072   // 32*64*64
#define DIM    64
#define KCB    512

// Output layout (concatenated, float32). Scalar perplexity misaligns
// everything after it to 4B -> scalar stores only into outE/outD.
#define OFF_Q 0
#define OFF_P (N_ROWS * DIM)
#define OFF_E (OFF_P + 1)
#define OFF_I (OFF_E + (size_t)N_ROWS * KCB)
#define OFF_D (OFF_I + N_ROWS)

#define CAND_CAP 16
#define CAND_MARGIN 1e-3f

// Scratch
__device__ float g_rownorm[N_ROWS];
__device__ float g_colnorm[KCB];
__device__ unsigned int g_count[KCB];
__device__ int g_candn[N_ROWS];
__device__ unsigned short g_cand[N_ROWS][CAND_CAP];

// ---------------------------------------------------------------------------
__device__ __forceinline__ unsigned int forder(float f) {
    unsigned int u = __float_as_uint(f);
    unsigned int mask = ((int)u >> 31) | 0x80000000u;
    return u ^ mask;  // monotonic float -> uint
}

__device__ __forceinline__ float cvt_tf32(float v) {
    unsigned r;
    asm("cvt.rna.tf32.f32 %0, %1;" : "=r"(r) : "f"(v));
    return __uint_as_float(r);
}

__device__ __forceinline__ void mma8(float* c, const float* a, const float* b) {
    asm volatile(
        "mma.sync.aligned.m16n8k8.row.col.f32.tf32.tf32.f32 "
        "{%0,%1,%2,%3}, {%4,%5,%6,%7}, {%8,%9}, {%0,%1,%2,%3};"
        : "+f"(c[0]), "+f"(c[1]), "+f"(c[2]), "+f"(c[3])
        : "r"(__float_as_uint(a[0])), "r"(__float_as_uint(a[1])),
          "r"(__float_as_uint(a[2])), "r"(__float_as_uint(a[3])),
          "r"(__float_as_uint(b[0])), "r"(__float_as_uint(b[1])));
}

// ---------------------------------------------------------------------------
__global__ void rownorm_k(const float* __restrict__ X) {
    int r = blockIdx.x * blockDim.x + threadIdx.x;
    if (r >= N_ROWS) return;
    g_candn[r] = 0;
    const float4* p = (const float4*)(X + (size_t)r * DIM);
    float s = 0.f;
#pragma unroll
    for (int i = 0; i < DIM / 4; i++) {
        float4 v = p[i];
        s += v.x * v.x + v.y * v.y + v.z * v.z + v.w * v.w;
    }
    g_rownorm[r] = s;
}

__global__ void colnorm_k(const float* __restrict__ CB) {
    int r = blockIdx.x * blockDim.x + threadIdx.x;
    if (r >= KCB) return;
    g_count[r] = 0u;
    const float4* p = (const float4*)(CB + (size_t)r * DIM);
    float s = 0.f;
#pragma unroll
    for (int i = 0; i < DIM / 4; i++) {
        float4 v = p[i];
        s += v.x * v.x + v.y * v.y + v.z * v.z + v.w * v.w;
    }
    g_colnorm[r] = s;
}

// ---------------------------------------------------------------------------
// tensor-core distance GEMM (single tf32 MMA) + candidate collection
// + encodings zero-fill.
// CTA tile 64 rows x 128 cols, K=64 resident. 256 thr = 8 warps, warp tile
// 32x32 (acc 32/thread -> ~64-72 regs -> 3-4 CTAs/SM, 2x+ occupancy).
// smem k-layout permuted in each 8-block: pos(k) = (k&3)*2 + (k>>2)
// -> fragment pairs (k=t, k=t+4) are one LDS.64.
// ---------------------------------------------------------------------------
#define AS_STRIDE 68
#define CS_STRIDE 132
#define GEMM_SMEM_BYTES ((64 + 128) * AS_STRIDE * 4)   // 52224

__global__ __launch_bounds__(256) void gemm_k(const float* __restrict__ A,
                                              const float* __restrict__ B,
                                              float* __restrict__ outD,
                                              float* __restrict__ outE,
                                              int bm_base) {
    extern __shared__ float sm[];
    float* As = sm;                      // [64][68] tf32(A), k-permuted
    float* Bs = sm + 64 * AS_STRIDE;     // [128][68] tf32(2*codebook), k-perm
    float* Cs = sm;                      // [64][132] aliases post-MMA

    const int tid = threadIdx.x;
    const int lane = tid & 31;
    const int wid = tid >> 5;
    const int g = lane >> 2;
    const int t = lane & 3;
    const int wm0 = (wid & 1) * 32;      // 2 warp rows
    const int wn0 = (wid >> 1) * 32;     // 4 warp cols
    const int bm0 = bm_base + blockIdx.y * 64;
    const int bk0 = blockIdx.x * 128;

    // Tile load + one-time tf32 cvt + k-permuted scatter.
    {
        const float4* Ag = (const float4*)(A + (size_t)bm0 * DIM);
        const float4* Bg = (const float4*)(B + (size_t)bk0 * DIM);
#pragma unroll
        for (int i = 0; i < 4; i++) {          // A: 64 rows = 1024 float4
            int t4 = tid + i * 256;
            int row = t4 >> 4;
            int c4 = (t4 & 15) * 4;
            int base = (c4 & ~7) + ((c4 & 4) >> 2);
            float* ap = &As[row * AS_STRIDE + base];
            float4 va = Ag[t4];
            ap[0] = cvt_tf32(va.x);
            ap[2] = cvt_tf32(va.y);
            ap[4] = cvt_tf32(va.z);
            ap[6] = cvt_tf32(va.w);
        }
#pragma unroll
        for (int i = 0; i < 8; i++) {          // B: 128 rows = 2048 float4
            int t4 = tid + i * 256;
            int row = t4 >> 4;
            int c4 = (t4 & 15) * 4;
            int base = (c4 & ~7) + ((c4 & 4) >> 2);
            float* bp = &Bs[row * AS_STRIDE + base];
            float4 vb = Bg[t4];
            bp[0] = cvt_tf32(2.f * vb.x);
            bp[2] = cvt_tf32(2.f * vb.y);
            bp[4] = cvt_tf32(2.f * vb.z);
            bp[6] = cvt_tf32(2.f * vb.w);
        }
    }
    __syncthreads();

    float acc[2][4][4];
#pragma unroll
    for (int mi = 0; mi < 2; mi++)
#pragma unroll
        for (int ni = 0; ni < 4; ni++)
#pragma unroll
            for (int j = 0; j < 4; j++) acc[mi][ni][j] = 0.f;

#pragma unroll
    for (int k0 = 0; k0 < 64; k0 += 8) {
        float ah[2][4];
#pragma unroll
        for (int mi = 0; mi < 2; mi++) {
            int r0 = wm0 + mi * 16 + g;
            float2 fa0 = *(const float2*)&As[r0 * AS_STRIDE + k0 + 2 * t];
            float2 fa1 = *(const float2*)&As[(r0 + 8) * AS_STRIDE + k0 + 2 * t];
            ah[mi][0] = fa0.x;
            ah[mi][1] = fa1.x;
            ah[mi][2] = fa0.y;
            ah[mi][3] = fa1.y;
        }
        float bh[4][2];
#pragma unroll
        for (int ni = 0; ni < 4; ni++) {
            int n = wn0 + ni * 8 + g;
            float2 fb = *(const float2*)&Bs[n * AS_STRIDE + k0 + 2 * t];
            bh[ni][0] = fb.x;
            bh[ni][1] = fb.y;
        }
#pragma unroll
        for (int mi = 0; mi < 2; mi++)
#pragma unroll
            for (int ni = 0; ni < 4; ni++)
                mma8(acc[mi][ni], ah[mi], bh[ni]);
    }

    __syncthreads();
    // Stage accumulators via STS.64 (c0 even -> 8B aligned)
#pragma unroll
    for (int mi = 0; mi < 2; mi++)
#pragma unroll
        for (int ni = 0; ni < 4; ni++) {
            int r0 = wm0 + mi * 16 + g;
            int c0 = wn0 + ni * 8 + 2 * t;
            *(float2*)&Cs[r0 * CS_STRIDE + c0] =
                make_float2(acc[mi][ni][0], acc[mi][ni][1]);
            *(float2*)&Cs[(r0 + 8) * CS_STRIDE + c0] =
                make_float2(acc[mi][ni][2], acc[mi][ni][3]);
        }
    __syncthreads();

    // Distance stores + candidate collection + encodings zero-fill.
    // 8 warps x 8 rows = 64 rows.
    float cn4[4];
#pragma unroll
    for (int j = 0; j < 4; j++) cn4[j] = g_colnorm[bk0 + lane + 32 * j];

#pragma unroll 2
    for (int r = 0; r < 8; r++) {
        int lr = wid * 8 + r;
        int gr = bm0 + lr;
        float rn = g_rownorm[gr];
        const float* crow = &Cs[lr * CS_STRIDE];
        float* drow = outD + (size_t)gr * KCB + bk0;
        float* erow = outE + (size_t)gr * KCB + bk0;
        float v[4];
        float mn = 3.4e38f;
#pragma unroll
        for (int j = 0; j < 4; j++) {
            int c = lane + 32 * j;
            float d = (rn - crow[c]) + cn4[j];
            v[j] = d;
            drow[c] = d;
            erow[c] = 0.f;
            if (d < mn) mn = d;
        }
#pragma unroll
        for (int off = 16; off > 0; off >>= 1) {
            float o = __shfl_xor_sync(0xFFFFFFFFu, mn, off);
            if (o < mn) mn = o;
        }
        float thr = mn + CAND_MARGIN;
#pragma unroll
        for (int j = 0; j < 4; j++) {
            if (v[j] <= thr) {
                int slot = atomicAdd(&g_candn[gr], 1);
                if (slot < CAND_CAP)
                    g_cand[gr][slot] = (unsigned short)(bk0 + lane + 32 * j);
            }
        }
    }
}

// ---------------------------------------------------------------------------
// rescue + outputs: block = 32 rows, 8 threads/row. Candidates processed
// serially by the 8-lane group (coalesced codebook reads), two at a time so
// the shfl-reduce chains pipeline. Per-8-group shfl masks.
// Exact fp32 numerics. Writes indices, histogram, one-hot 1.0, quantized.
// ---------------------------------------------------------------------------
#define RROWS 32   // rows per block
__global__ __launch_bounds__(256, 4) void rescue_k(const float* __restrict__ X,
                                                   const float* __restrict__ CB,
                                                   float* __restrict__ outI,
                                                   float* __restrict__ outE,
                                                   float* __restrict__ outQ) {
    __shared__ float Xs[RROWS * DIM];           // 8 KB
    const int tid = threadIdx.x;
    const int r = tid >> 3;        // 0..31 row within block
    const int s = tid & 7;         // lane within row group
    const int lane = tid & 31;
    const unsigned gmask = 0xFFu << (lane & 24);   // this 8-group's lanes
    const int row0 = blockIdx.x * RROWS;
    const int gr = row0 + r;

    // cooperative X stage: 32 rows x 64 floats = 512 float4
    {
        const float4* Xg = (const float4*)(X + (size_t)row0 * DIM);
        float4* Xs4 = (float4*)Xs;
#pragma unroll
        for (int i = 0; i < 2; i++) Xs4[tid + i * 256] = Xg[tid + i * 256];
    }
    __syncthreads();

    const float rn = g_rownorm[gr];
    const float4* xp4 = (const float4*)(Xs + r * DIM);
    const int n = g_candn[gr];

    unsigned long long best = 0xFFFFFFFFFFFFFFFFULL;
    if (n <= CAND_CAP) {
        float4 x0 = xp4[s * 2];
        float4 x1 = xp4[s * 2 + 1];
        int j = 0;
        for (; j + 1 < n; j += 2) {
            int c0 = g_cand[gr][j];
            int c1 = g_cand[gr][j + 1];
            const float4* e0p = (const float4*)(CB + (size_t)c0 * DIM);
            const float4* e1p = (const float4*)(CB + (size_t)c1 * DIM);
            float4 a0 = e0p[s * 2], a1 = e0p[s * 2 + 1];
            float4 b0 = e1p[s * 2], b1 = e1p[s * 2 + 1];
            float p = x0.x * a0.x;
            p = fmaf(x0.y, a0.y, p); p = fmaf(x0.z, a0.z, p);
            p = fmaf(x0.w, a0.w, p); p = fmaf(x1.x, a1.x, p);
            p = fmaf(x1.y, a1.y, p); p = fmaf(x1.z, a1.z, p);
            p = fmaf(x1.w, a1.w, p);
            float q = x0.x * b0.x;
            q = fmaf(x0.y, b0.y, q); q = fmaf(x0.z, b0.z, q);
            q = fmaf(x0.w, b0.w, q); q = fmaf(x1.x, b1.x, q);
            q = fmaf(x1.y, b1.y, q); q = fmaf(x1.z, b1.z, q);
            q = fmaf(x1.w, b1.w, q);
            p += __shfl_xor_sync(gmask, p, 4);
            q += __shfl_xor_sync(gmask, q, 4);
            p += __shfl_xor_sync(gmask, p, 2);
            q += __shfl_xor_sync(gmask, q, 2);
            p += __shfl_xor_sync(gmask, p, 1);
            q += __shfl_xor_sync(gmask, q, 1);
            float d0 = (rn - 2.f * p) + g_colnorm[c0];
            float d1 = (rn - 2.f * q) + g_colnorm[c1];
            unsigned long long k0 =
                ((unsigned long long)forder(d0) << 32) | (unsigned)c0;
            unsigned long long k1 =
                ((unsigned long long)forder(d1) << 32) | (unsigned)c1;
            if (k0 < best) best = k0;
            if (k1 < best) best = k1;
        }
        if (j < n) {
            int c0 = g_cand[gr][j];
            const float4* e0p = (const float4*)(CB + (size_t)c0 * DIM);
            float4 a0 = e0p[s * 2], a1 = e0p[s * 2 + 1];
            float p = x0.x * a0.x;
            p = fmaf(x0.y, a0.y, p); p = fmaf(x0.z, a0.z, p);
            p = fmaf(x0.w, a0.w, p); p = fmaf(x1.x, a1.x, p);
            p = fmaf(x1.y, a1.y, p); p = fmaf(x1.z, a1.z, p);
            p = fmaf(x1.w, a1.w, p);
            p += __shfl_xor_sync(gmask, p, 4);
            p += __shfl_xor_sync(gmask, p, 2);
            p += __shfl_xor_sync(gmask, p, 1);
            float d0 = (rn - 2.f * p) + g_colnorm[c0];
            unsigned long long k0 =
                ((unsigned long long)forder(d0) << 32) | (unsigned)c0;
            if (k0 < best) best = k0;
        }
    } else {
        // overflow fallback (rare): per-lane scan of all 512 codes
        for (int c = s; c < KCB; c += 8) {
            const float4* cp4 = (const float4*)(CB + (size_t)c * DIM);
            float d0 = 0.f, d1 = 0.f, d2 = 0.f, d3 = 0.f;
#pragma unroll
            for (int i = 0; i < DIM / 4; i++) {
                float4 x = xp4[i];
                float4 e = cp4[i];
                d0 = fmaf(x.x, e.x, d0);
                d1 = fmaf(x.y, e.y, d1);
                d2 = fmaf(x.z, e.z, d2);
                d3 = fmaf(x.w, e.w, d3);
            }
            float dot = (d0 + d1) + (d2 + d3);
            float d = (rn - 2.f * dot) + g_colnorm[c];
            unsigned long long key =
                ((unsigned long long)forder(d) << 32) | (unsigned)c;
            if (key < best) best = key;
        }
#pragma unroll
        for (int off = 4; off > 0; off >>= 1) {
            unsigned long long o = __shfl_xor_sync(gmask, best, off);
            if (o < best) best = o;
        }
    }
    int idx = (int)(best & 0xFFFFFFFFu);

    if (s == 0) {
        outI[gr] = (float)idx;
        atomicAdd(&g_count[idx], 1u);
        outE[(size_t)gr * KCB + idx] = 1.f;  // zeros pre-filled by gemm_k
    }

    // quantized: 8 threads x 8 floats (2 float4 each); outQ 16B-aligned
    {
        const float4* cp4 = (const float4*)(CB + (size_t)idx * DIM);
        float4* qp4 = (float4*)(outQ + (size_t)gr * DIM);
#pragma unroll
        for (int i = 0; i < 2; i++) {
            int j = s * 2 + i;
            float4 x = xp4[j];
            float4 e = cp4[j];
            float4 q;
            q.x = x.x + (e.x - x.x);
            q.y = x.y + (e.y - x.y);
            q.z = x.z + (e.z - x.z);
            q.w = x.w + (e.w - x.w);
            qp4[j] = q;
        }
    }
}

// ---------------------------------------------------------------------------
__global__ void perp_k(float* __restrict__ outP) {
    __shared__ float s[KCB];
    int t = threadIdx.x;
    float p = (float)g_count[t] / (float)N_ROWS;
    s[t] = p * logf(p + 1e-10f);
    __syncthreads();
    for (int o = KCB / 2; o > 0; o >>= 1) {
        if (t < o) s[t] += s[t + o];
        __syncthreads();
    }
    if (t == 0) outP[0] = expf(-s[0]);
}

// ---------------------------------------------------------------------------
extern "C" void kernel_launch(void* const* d_in, const int* in_sizes, int n_in,
                              void* d_out, int out_size) {
    const float* X = (const float*)d_in[0];
    const float* CB = (const float*)d_in[1];
    if (n_in >= 2 && in_sizes[0] == KCB * DIM) {
        X = (const float*)d_in[1];
        CB = (const float*)d_in[0];
    }
    float* out = (float*)d_out;
    float* outQ = out + OFF_Q;
    float* outP = out + OFF_P;
    float* outE = out + OFF_E;
    float* outI = out + OFF_I;
    float* outD = out + OFF_D;

    cudaFuncSetAttribute(gemm_k, cudaFuncAttributeMaxDynamicSharedMemorySize,
                         GEMM_SMEM_BYTES);

    rownorm_k<<<N_ROWS / 256, 256>>>(X);
    colnorm_k<<<2, 256>>>(CB);
    // split gemm across two launches (also lands gemm in the ncu capture slot)
    dim3 ggrid(KCB / 128, N_ROWS / 64 / 2);
    gemm_k<<<ggrid, 256, GEMM_SMEM_BYTES>>>(X, CB, outD, outE, 0);
    gemm_k<<<ggrid, 256, GEMM_SMEM_BYTES>>>(X, CB, outD, outE, N_ROWS / 2);
    rescue_k<<<N_ROWS / RROWS, 256>>>(X, CB, outI, outE, outQ);
    perp_k<<<1, KCB>>>(outP);
}